// round 11
// baseline (speedup 1.0000x reference)
#include <cuda_runtime.h>
#include <cuda_fp16.h>
#include <math.h>
#include <stdint.h>

#define B_  4
#define N_  2048
#define D_  256
#define H_  4
#define E_  256
#define M_  (B_*N_)          // 8192 rows
#define HB_ (H_*B_)          // 16
#define PADV (-2.0f)
#define EPS_ 1e-6f
#define CL2E 0.09016844f     // (1/sqrt(256)) * log2(e)  — folded into Q

// ---------------- scratch (device globals; no runtime alloc) ----------------
__device__ __half g_xnh[(size_t)M_*D_];          // LN(x) fp16
__device__ __half g_qh [(size_t)HB_*N_*E_];      // Q*CL2E fp16 [h][m][e]
__device__ __half g_kh [(size_t)HB_*N_*E_];      // K fp16 [h][m][e]
__device__ __half g_vt [(size_t)HB_*E_*N_];      // V^T fp16 [h][b][e][n]
__device__ __half g_gth[(size_t)HB_*N_*E_];      // gate pre-activation fp16
__device__ __half g_yh [(size_t)M_*H_*E_];       // concat fp16 [m][h*E+e]
__device__ __half g_wh [(size_t)4*H_*D_*E_];     // qkvg weights fp16 [t][h][d][e]
__device__ __half g_w1h[(size_t)H_*E_*E_];       // out_w fp16, rows permuted to [h*E+e]

// =================== PTX helpers (compute_103-safe) ===================
__device__ __forceinline__ uint32_t s2u(const void* p){
    uint32_t a;
    asm("{ .reg .u64 t; cvta.to.shared.u64 t, %1; cvt.u32.u64 %0, t; }" : "=r"(a) : "l"(p));
    return a;
}
__device__ __forceinline__ void cp16(uint32_t s, const void* g){
    asm volatile("cp.async.cg.shared.global [%0], [%1], 16;" :: "r"(s), "l"(g));
}
__device__ __forceinline__ void cp_commit(){ asm volatile("cp.async.commit_group;" ::: "memory"); }
template<int NN> __device__ __forceinline__ void cp_wait(){
    asm volatile("cp.async.wait_group %0;" :: "n"(NN) : "memory");
}
__device__ __forceinline__ void ldsm_x4(uint32_t& r0, uint32_t& r1, uint32_t& r2, uint32_t& r3, uint32_t addr){
    asm volatile("ldmatrix.sync.aligned.m8n8.x4.shared.b16 {%0,%1,%2,%3}, [%4];"
        : "=r"(r0), "=r"(r1), "=r"(r2), "=r"(r3) : "r"(addr));
}
__device__ __forceinline__ void ldsm_x2(uint32_t& r0, uint32_t& r1, uint32_t addr){
    asm volatile("ldmatrix.sync.aligned.m8n8.x2.shared.b16 {%0,%1}, [%2];"
        : "=r"(r0), "=r"(r1) : "r"(addr));
}
__device__ __forceinline__ void ldsm_x4t(uint32_t& r0, uint32_t& r1, uint32_t& r2, uint32_t& r3, uint32_t addr){
    asm volatile("ldmatrix.sync.aligned.m8n8.x4.trans.shared.b16 {%0,%1,%2,%3}, [%4];"
        : "=r"(r0), "=r"(r1), "=r"(r2), "=r"(r3) : "r"(addr));
}
__device__ __forceinline__ void mma16816(float c[4], uint32_t a0, uint32_t a1, uint32_t a2, uint32_t a3,
                                         uint32_t b0, uint32_t b1){
    asm volatile("mma.sync.aligned.m16n8k16.row.col.f32.f16.f16.f32 "
        "{%0,%1,%2,%3}, {%4,%5,%6,%7}, {%8,%9}, {%0,%1,%2,%3};"
        : "+f"(c[0]), "+f"(c[1]), "+f"(c[2]), "+f"(c[3])
        : "r"(a0), "r"(a1), "r"(a2), "r"(a3), "r"(b0), "r"(b1));
}
// fp16-accumulator MMA (2x rate)
__device__ __forceinline__ void mma16816h(uint32_t c[2], uint32_t a0, uint32_t a1, uint32_t a2, uint32_t a3,
                                          uint32_t b0, uint32_t b1){
    asm volatile("mma.sync.aligned.m16n8k16.row.col.f16.f16.f16.f16 "
        "{%0,%1}, {%2,%3,%4,%5}, {%6,%7}, {%0,%1};"
        : "+r"(c[0]), "+r"(c[1])
        : "r"(a0), "r"(a1), "r"(a2), "r"(a3), "r"(b0), "r"(b1));
}
__device__ __forceinline__ uint32_t pack2(float hi, float lo){
    uint32_t d; asm("cvt.rn.f16x2.f32 %0, %1, %2;" : "=r"(d) : "f"(hi), "f"(lo)); return d;
}
__device__ __forceinline__ uint32_t ex2h2(uint32_t a){
    uint32_t d; asm("ex2.approx.f16x2 %0, %1;" : "=r"(d) : "r"(a)); return d;
}
__device__ __forceinline__ uint32_t mulh2(uint32_t a, uint32_t b){
    uint32_t d; asm("mul.f16x2 %0, %1, %2;" : "=r"(d) : "r"(a), "r"(b)); return d;
}

// ---------------- warp row-reduction helper ----------------------------------
__device__ __forceinline__ void warp_meanvar(float s, float s2, float& mean, float& var){
    #pragma unroll
    for (int o = 16; o; o >>= 1) {
        s  += __shfl_xor_sync(0xffffffffu, s,  o);
        s2 += __shfl_xor_sync(0xffffffffu, s2, o);
    }
    mean = s * (1.0f / 256.0f);
    var  = s2 * (1.0f / 256.0f) - mean * mean;
}

// ---------------- K1: fused input LN (warp/row) + weight fp16 conversion -----
__global__ void __launch_bounds__(256) prep_k(const float* __restrict__ x,
                        const float* __restrict__ g, const float* __restrict__ b,
                        const float* __restrict__ Wq, const float* __restrict__ Wk,
                        const float* __restrict__ Wv, const float* __restrict__ Wg,
                        const float* __restrict__ ow) {
    if (blockIdx.x < M_ / 8) {
        int row = blockIdx.x * 8 + (threadIdx.x >> 5);
        int lane = threadIdx.x & 31;
        const float4* xr = (const float4*)(x + (size_t)row * D_) + lane * 2;
        float4 v0 = xr[0], v1 = xr[1];
        float s  = v0.x + v0.y + v0.z + v0.w + v1.x + v1.y + v1.z + v1.w;
        float s2 = v0.x*v0.x + v0.y*v0.y + v0.z*v0.z + v0.w*v0.w
                 + v1.x*v1.x + v1.y*v1.y + v1.z*v1.z + v1.w*v1.w;
        float mean, var; warp_meanvar(s, s2, mean, var);
        float rs = rsqrtf(var + EPS_);
        float4 g0 = ((const float4*)g)[lane*2], g1 = ((const float4*)g)[lane*2+1];
        float4 b0 = ((const float4*)b)[lane*2], b1 = ((const float4*)b)[lane*2+1];
        uint32_t o[4];
        o[0] = pack2((v0.y-mean)*rs*g0.y+b0.y, (v0.x-mean)*rs*g0.x+b0.x);
        o[1] = pack2((v0.w-mean)*rs*g0.w+b0.w, (v0.z-mean)*rs*g0.z+b0.z);
        o[2] = pack2((v1.y-mean)*rs*g1.y+b1.y, (v1.x-mean)*rs*g1.x+b1.x);
        o[3] = pack2((v1.w-mean)*rs*g1.w+b1.w, (v1.z-mean)*rs*g1.z+b1.z);
        *(uint4*)(g_xnh + (size_t)row * D_ + lane * 8) = *(uint4*)o;
    } else {
        int wb = blockIdx.x - M_ / 8;
        int t = wb >> 8;
        const float* src = (t == 0) ? Wq : (t == 1) ? Wk : (t == 2) ? Wv : (t == 3) ? Wg : ow;
        int idx = ((wb & 255) * 256 + threadIdx.x) * 4;
        float4 v = *(const float4*)(src + idx);
        __half2 h0 = __floats2half2_rn(v.x, v.y), h1 = __floats2half2_rn(v.z, v.w);
        if (t < 4) {
            __half2* d2 = (__half2*)(g_wh + (size_t)t * (H_ * D_ * E_) + idx);
            d2[0] = h0; d2[1] = h1;
        } else {
            int rr = idx >> 8, col = idx & 255;       // src row = e*H + h
            int e = rr >> 2, h = rr & 3;
            __half2* d2 = (__half2*)(g_w1h + (size_t)(h * E_ + e) * E_ + col);
            d2[0] = h0; d2[1] = h1;
        }
    }
}

// =================== HMMA GEMM mainloop: 128 x 256 tile, m32n128/warp ========
#define HG_LDA 72
#define HG_LDB 264
#define HG_BS_OFF 36864
#define HG_SMEM 104448
#define VT_LDT 136

__device__ __forceinline__ void hg_load(const __half* A, int ldA, const __half* Bg,
                                        uint32_t sA, uint32_t sB, int c, int buf, int tid){
    #pragma unroll
    for (int it = 0; it < 4; it++){
        int idx = tid + it * 256;
        int row = idx >> 3, cg = idx & 7;
        cp16(sA + (uint32_t)(buf * 128 * HG_LDA + row * HG_LDA + cg * 8) * 2,
             A + (size_t)row * ldA + c * 64 + cg * 8);
    }
    #pragma unroll
    for (int it = 0; it < 8; it++){
        int idx = tid + it * 256;
        int row = idx >> 5, cg = idx & 31;
        cp16(sB + (uint32_t)(buf * 64 * HG_LDB + row * HG_LDB + cg * 8) * 2,
             Bg + (size_t)(c * 64 + row) * 256 + cg * 8);
    }
    cp_commit();
}

__device__ __forceinline__ void hgemm_main(const __half* A, int ldA, const __half* Bg,
                                           int NC, char* smem, float acc[2][16][4]){
    const int tid = threadIdx.x, lane = tid & 31, warp = tid >> 5;
    const int wm = warp & 3, wn = warp >> 2;
    const uint32_t sA = s2u(smem), sB = s2u(smem + HG_BS_OFF);
    #pragma unroll
    for (int mi = 0; mi < 2; mi++)
        #pragma unroll
        for (int i = 0; i < 16; i++)
            #pragma unroll
            for (int j = 0; j < 4; j++) acc[mi][i][j] = 0.f;

    hg_load(A, ldA, Bg, sA, sB, 0, 0, tid);
    hg_load(A, ldA, Bg, sA, sB, 1, 1, tid);

    const int grp = lane >> 3, r8 = lane & 7;
    uint32_t aoff[2];
    #pragma unroll
    for (int mi = 0; mi < 2; mi++)
        aoff[mi] = (uint32_t)((wm * 32 + mi * 16 + (lane & 15)) * HG_LDA + (lane >> 4) * 8) * 2;
    const uint32_t boff = (uint32_t)(((grp & 1) * 8 + r8) * HG_LDB + wn * 128 + ((grp & 2) ? 8 : 0)) * 2;

    for (int c = 0; c < NC; c++){
        if (c + 1 < NC) cp_wait<1>(); else cp_wait<0>();
        __syncthreads();
        const uint32_t sa = sA + (uint32_t)((c & 1) * 128 * HG_LDA * 2);
        const uint32_t sb = sB + (uint32_t)((c & 1) * 64 * HG_LDB * 2) + boff;
        #pragma unroll
        for (int ks = 0; ks < 4; ks++){
            uint32_t a[2][4];
            #pragma unroll
            for (int mi = 0; mi < 2; mi++)
                ldsm_x4(a[mi][0], a[mi][1], a[mi][2], a[mi][3], sa + aoff[mi] + (uint32_t)(ks * 32));
            #pragma unroll
            for (int nb = 0; nb < 8; nb++){
                uint32_t b0, b1, b2, b3;
                ldsm_x4t(b0, b1, b2, b3, sb + (uint32_t)(ks * 16 * HG_LDB + nb * 16) * 2);
                #pragma unroll
                for (int mi = 0; mi < 2; mi++){
                    mma16816(acc[mi][2 * nb],     a[mi][0], a[mi][1], a[mi][2], a[mi][3], b0, b1);
                    mma16816(acc[mi][2 * nb + 1], a[mi][0], a[mi][1], a[mi][2], a[mi][3], b2, b3);
                }
            }
        }
        __syncthreads();
        if (c + 2 < NC) hg_load(A, ldA, Bg, sA, sB, c + 2, c & 1, tid);
    }
}

// ---------------- K2: Q/K/V/gate projections (HMMA) --------------------------
__global__ void __launch_bounds__(256, 1) qkvg_h_k()
{
    extern __shared__ char smem[];
    const int z = blockIdx.y, h = z >> 2, t = z & 3;
    const int m0 = blockIdx.x * 128;
    const int tid = threadIdx.x, lane = tid & 31, warp = tid >> 5;
    const int wm = warp & 3, wn = warp >> 2;
    const __half* A = g_xnh + (size_t)m0 * D_;
    const __half* W = g_wh + ((size_t)t * H_ + h) * D_ * E_;
    float acc[2][16][4];
    hgemm_main(A, D_, W, 4, smem, acc);

    if (t != 2) {
        __half* C = (t == 0 ? g_qh : t == 1 ? g_kh : g_gth) + (size_t)h * M_ * E_;
        const float sc = (t == 0) ? CL2E : 1.0f;
        #pragma unroll
        for (int mi = 0; mi < 2; mi++){
            int r0 = m0 + wm * 32 + mi * 16 + (lane >> 2), r1 = r0 + 8;
            #pragma unroll
            for (int nb = 0; nb < 8; nb++)
                #pragma unroll
                for (int t2 = 0; t2 < 2; t2++){
                    int col = wn * 128 + nb * 16 + t2 * 8 + (lane & 3) * 2;
                    const float* a = acc[mi][nb * 2 + t2];
                    *(__half2*)&C[(size_t)r0 * E_ + col] = __floats2half2_rn(a[0] * sc, a[1] * sc);
                    *(__half2*)&C[(size_t)r1 * E_ + col] = __floats2half2_rn(a[2] * sc, a[3] * sc);
                }
        }
    } else {
        __half* st = (__half*)smem;
        __syncthreads();
        #pragma unroll
        for (int mi = 0; mi < 2; mi++){
            int r0 = wm * 32 + mi * 16 + (lane >> 2), r1 = r0 + 8;
            #pragma unroll
            for (int nb = 0; nb < 8; nb++)
                #pragma unroll
                for (int t2 = 0; t2 < 2; t2++){
                    int col = wn * 128 + nb * 16 + t2 * 8 + (lane & 3) * 2;
                    const float* a = acc[mi][nb * 2 + t2];
                    st[(col    ) * VT_LDT + r0] = __float2half_rn(a[0]);
                    st[(col + 1) * VT_LDT + r0] = __float2half_rn(a[1]);
                    st[(col    ) * VT_LDT + r1] = __float2half_rn(a[2]);
                    st[(col + 1) * VT_LDT + r1] = __float2half_rn(a[3]);
                }
        }
        __syncthreads();
        const int bidx = m0 >> 11, n0 = m0 & (N_ - 1);
        __half* dst = g_vt + (size_t)(h * B_ + bidx) * E_ * N_;
        #pragma unroll
        for (int i = 0; i < 16; i++){
            int chunk = tid + i * 256;
            int e = chunk >> 4, off = (chunk & 15) * 8;
            *(uint4*)&dst[(size_t)e * N_ + n0 + off] = *(uint4*)&st[e * VT_LDT + off];
        }
    }
}

// ===== K3: HMMA flash attention (S/PV pipelined) + fused gate/res/LN epilog ==
#define LDK 264
#define LDV 72
#define AT_Q   0
#define AT_K   (128 * LDK)                 // 2 bufs of 64*LDK
#define AT_V   (AT_K + 2 * 64 * LDK)       // 2 bufs of 256*LDV
#define AT_ONE (AT_V + 2 * 256 * LDV)      // 8*LDV (row0=ones)
#define AT_KM  (AT_ONE + 8 * LDV)          // 2048 halves (1024 u32) full key mask
#define AT_H   (AT_KM + 2048)
#define AT_SMEM (AT_H * 2)                 // 214144 bytes

__device__ __forceinline__ void expconv_h(const uint32_t S[8][2], uint32_t pa[4][4],
                                          const uint32_t* kmbase, int lane){
    #pragma unroll
    for (int nb = 0; nb < 8; nb++) {
        uint32_t km = kmbase[nb * 4 + (lane & 3)];
        pa[nb >> 1][(nb & 1) * 2]     = mulh2(ex2h2(S[nb][0]), km);
        pa[nb >> 1][(nb & 1) * 2 + 1] = mulh2(ex2h2(S[nb][1]), km);
    }
}

__global__ void __launch_bounds__(256, 1) attn_mma_k(const float* __restrict__ mask,
                        const float* __restrict__ x,
                        const float* __restrict__ gr, const float* __restrict__ br)
{
    extern __shared__ __half sm[];
    const int tid = threadIdx.x, lane = tid & 31, warp = tid >> 5;
    const int qt = blockIdx.x, hb = blockIdx.y, bidx = hb & (B_ - 1);
    const int h = hb >> 2;
    const int qbase = qt * 128;
    const __half* Qg = g_qh + (size_t)hb * N_ * E_ + (size_t)qbase * E_;
    const __half* Kg = g_kh + (size_t)hb * N_ * E_;
    const __half* Vt = g_vt + (size_t)hb * E_ * N_;
    const float* mrow = mask + (size_t)bidx * N_;

    const uint32_t sQ = s2u(sm + AT_Q);
    const uint32_t sK = s2u(sm + AT_K);
    const uint32_t sV = s2u(sm + AT_V);
    const uint32_t sONE = s2u(sm + AT_ONE);
    uint32_t* kmarr = (uint32_t*)(sm + AT_KM);

    if (tid < 288) ((uint32_t*)(sm + AT_ONE))[tid] = (tid < 36) ? 0x3C003C00u : 0u;
    #pragma unroll
    for (int j = 0; j < 4; j++) {
        float a = mrow[tid * 8 + 2 * j], b = mrow[tid * 8 + 2 * j + 1];
        __half2 km = __floats2half2_rn((a == PADV) ? 0.f : 1.f, (b == PADV) ? 0.f : 1.f);
        kmarr[tid * 4 + j] = *(uint32_t*)&km;
    }

    // prologue: Q | K0 | V0 | K1 | V1 as 5 separate cp.async groups
    #pragma unroll
    for (int it = 0; it < 16; it++) {
        int idx = tid + it * 256;
        int row = idx >> 5, c = idx & 31;
        cp16(sQ + (uint32_t)(row * LDK + c * 8) * 2, Qg + (size_t)row * E_ + c * 8);
    }
    cp_commit();
    #pragma unroll
    for (int buf = 0; buf < 2; buf++) {
        #pragma unroll
        for (int it = 0; it < 8; it++) {
            int idx = tid + it * 256;
            int row = idx >> 5, c = idx & 31;
            cp16(sK + (uint32_t)(buf * 64 * LDK + row * LDK + c * 8) * 2,
                 Kg + (size_t)(buf * 64 + row) * E_ + c * 8);
        }
        cp_commit();
        #pragma unroll
        for (int it = 0; it < 8; it++) {
            int idx = tid + it * 256;
            int e = idx >> 3, c = idx & 7;
            cp16(sV + (uint32_t)(buf * 256 * LDV + e * LDV + c * 8) * 2,
                 Vt + (size_t)e * N_ + buf * 64 + c * 8);
        }
        cp_commit();
    }

    const int grp = lane >> 3, r8 = lane & 7;
    const int moff = (grp & 2) ? 8 : 0;
    const int koff = (grp & 1) ? 8 : 0;
    const uint32_t qaddr0 = sQ + (uint32_t)((warp * 16 + (lane & 15)) * LDK + (lane >> 4) * 8) * 2;
    const uint32_t kaddr0 = sK + (uint32_t)((moff + r8) * LDK + koff) * 2;
    const uint32_t vaddr0 = sV + (uint32_t)((moff + r8) * LDV + koff) * 2;
    const uint32_t exaddr = sONE + (uint32_t)((lane & 7) * LDV + ((lane >> 3) & 1) * 8) * 2;

    float O[32][4];
    #pragma unroll
    for (int i = 0; i < 32; i++)
        #pragma unroll
        for (int j = 0; j < 4; j++) O[i][j] = 0.f;
    float Oex[4] = {0.f, 0.f, 0.f, 0.f};
    uint32_t pa[4][4];

    // ---- preamble: S(0) -> pa (fp16 accumulation) ----
    cp_wait<3>();
    __syncthreads();
    {
        uint32_t S[8][2];
        #pragma unroll
        for (int i = 0; i < 8; i++) { S[i][0] = 0u; S[i][1] = 0u; }
        #pragma unroll
        for (int ks = 0; ks < 16; ks++) {
            uint32_t q0, q1, q2, q3;
            ldsm_x4(q0, q1, q2, q3, qaddr0 + (uint32_t)(ks * 32));
            #pragma unroll
            for (int nbp = 0; nbp < 4; nbp++) {
                uint32_t b0, b1, b2, b3;
                ldsm_x4(b0, b1, b2, b3, kaddr0 + (uint32_t)(nbp * 16 * LDK * 2 + ks * 32));
                mma16816h(S[2 * nbp],     q0, q1, q2, q3, b0, b1);
                mma16816h(S[2 * nbp + 1], q0, q1, q2, q3, b2, b3);
            }
        }
        expconv_h(S, pa, kmarr, lane);
    }

    // ---- main loop: PV(kc) interleaved with S(kc+1); K prefetch hoisted ----
    for (int kc = 0; kc < 32; kc++) {
        if (kc == 31) cp_wait<0>(); else cp_wait<1>();
        __syncthreads();

        if (kc + 2 < 32) {
            const int nb2 = kc * 64 + 128;
            #pragma unroll
            for (int it = 0; it < 8; it++) {
                int idx = tid + it * 256;
                int row = idx >> 5, c = idx & 31;
                cp16(sK + (uint32_t)((kc & 1) * 64 * LDK + row * LDK + c * 8) * 2,
                     Kg + (size_t)(nb2 + row) * E_ + c * 8);
            }
            cp_commit();
        }

        const uint32_t kbN = kaddr0 + (uint32_t)(((kc + 1) & 1) * 64 * LDK) * 2;
        const uint32_t vb  = vaddr0 + (uint32_t)((kc & 1) * 256 * LDV) * 2;

        if (kc < 31) {
            uint32_t S[8][2];
            #pragma unroll
            for (int i = 0; i < 8; i++) { S[i][0] = 0u; S[i][1] = 0u; }
            #pragma unroll
            for (int i = 0; i < 16; i++) {
                uint32_t q0, q1, q2, q3;
                ldsm_x4(q0, q1, q2, q3, qaddr0 + (uint32_t)(i * 32));
                #pragma unroll
                for (int nbp = 0; nbp < 4; nbp++) {
                    uint32_t b0, b1, b2, b3;
                    ldsm_x4(b0, b1, b2, b3, kbN + (uint32_t)(nbp * 16 * LDK * 2 + i * 32));
                    mma16816h(S[2 * nbp],     q0, q1, q2, q3, b0, b1);
                    mma16816h(S[2 * nbp + 1], q0, q1, q2, q3, b2, b3);
                }
                #pragma unroll
                for (int ks2 = 0; ks2 < 4; ks2++) {
                    uint32_t v0, v1, v2, v3;
                    ldsm_x4(v0, v1, v2, v3, vb + (uint32_t)(i * 16 * LDV * 2 + ks2 * 32));
                    mma16816(O[2 * i],     pa[ks2][0], pa[ks2][1], pa[ks2][2], pa[ks2][3], v0, v1);
                    mma16816(O[2 * i + 1], pa[ks2][0], pa[ks2][1], pa[ks2][2], pa[ks2][3], v2, v3);
                }
            }
            #pragma unroll
            for (int ks2 = 0; ks2 < 4; ks2++) {
                uint32_t e0, e1;
                ldsm_x2(e0, e1, exaddr + (uint32_t)(ks2 * 32));
                mma16816(Oex, pa[ks2][0], pa[ks2][1], pa[ks2][2], pa[ks2][3], e0, e1);
            }
            expconv_h(S, pa, kmarr + (kc + 1) * 32, lane);

            __syncthreads();
            if (kc + 2 < 32) {
                const int nb2 = kc * 64 + 128;
                #pragma unroll
                for (int it = 0; it < 8; it++) {
                    int idx = tid + it * 256;
                    int e = idx >> 3, c = idx & 7;
                    cp16(sV + (uint32_t)((kc & 1) * 256 * LDV + e * LDV + c * 8) * 2,
                         Vt + (size_t)e * N_ + nb2 + c * 8);
                }
                cp_commit();
            }
        } else {
            #pragma unroll
            for (int i = 0; i < 16; i++) {
                #pragma unroll
                for (int ks2 = 0; ks2 < 4; ks2++) {
                    uint32_t v0, v1, v2, v3;
                    ldsm_x4(v0, v1, v2, v3, vb + (uint32_t)(i * 16 * LDV * 2 + ks2 * 32));
                    mma16816(O[2 * i],     pa[ks2][0], pa[ks2][1], pa[ks2][2], pa[ks2][3], v0, v1);
                    mma16816(O[2 * i + 1], pa[ks2][0], pa[ks2][1], pa[ks2][2], pa[ks2][3], v2, v3);
                }
            }
            #pragma unroll
            for (int ks2 = 0; ks2 < 4; ks2++) {
                uint32_t e0, e1;
                ldsm_x2(e0, e1, exaddr + (uint32_t)(ks2 * 32));
                mma16816(Oex, pa[ks2][0], pa[ks2][1], pa[ks2][2], pa[ks2][3], e0, e1);
            }
        }
    }

    // ---- fused finalize: normalize O, gate, +x residual, per-row LN -> g_yh --
    float l0 = __shfl_sync(0xffffffffu, Oex[0], lane & ~3);
    float l1 = __shfl_sync(0xffffffffu, Oex[2], lane & ~3);
    const int rl0 = warp * 16 + (lane >> 2);
    float invr[2];
    invr[0] = ((mrow[qbase + rl0]     == PADV) ? 0.f : 1.f) / fmaxf(l0, 1e-30f);
    invr[1] = ((mrow[qbase + rl0 + 8] == PADV) ? 0.f : 1.f) / fmaxf(l1, 1e-30f);

    #pragma unroll
    for (int r = 0; r < 2; r++) {
        const int rg = qbase + rl0 + r * 8;                 // row within N_
        const size_t mg = (size_t)bidx * N_ + rg;           // global row
        const float inv = invr[r];
        const __half2* gt = (const __half2*)(g_gth + ((size_t)hb * N_ + rg) * E_);
        const float* xr = x + mg * D_;
        float s = 0.f, s2 = 0.f;
        // pass 1: t = O*inv*sigmoid(gate) + x, in place; accumulate stats
        #pragma unroll
        for (int eb = 0; eb < 32; eb++) {
            int col = eb * 8 + (lane & 3) * 2;
            float2 gv = __half22float2(gt[col >> 1]);
            float2 xv = *(const float2*)&xr[col];
            float sg0 = 1.f / (1.f + __expf(-gv.x));
            float sg1 = 1.f / (1.f + __expf(-gv.y));
            float t0 = O[eb][r * 2]     * inv * sg0 + xv.x;
            float t1 = O[eb][r * 2 + 1] * inv * sg1 + xv.y;
            O[eb][r * 2] = t0; O[eb][r * 2 + 1] = t1;
            s += t0 + t1; s2 += t0 * t0 + t1 * t1;
        }
        // quad reduction (4 lanes hold the 256 columns of this row)
        #pragma unroll
        for (int o = 1; o <= 2; o <<= 1) {
            s  += __shfl_xor_sync(0xffffffffu, s,  o);
            s2 += __shfl_xor_sync(0xffffffffu, s2, o);
        }
        float mean = s * (1.f / 256.f);
        float var  = s2 * (1.f / 256.f) - mean * mean;
        float rs = rsqrtf(var + EPS_);
        // pass 2: yn = (t-mean)*rs*gr+br -> g_yh[m][h*E+col]
        __half* dst = g_yh + mg * (H_ * E_) + h * E_;
        #pragma unroll
        for (int eb = 0; eb < 32; eb++) {
            int col = eb * 8 + (lane & 3) * 2;
            float2 gg = *(const float2*)&gr[col];
            float2 bb = *(const float2*)&br[col];
            *(__half2*)&dst[col] = __floats2half2_rn(
                (O[eb][r * 2]     - mean) * rs * gg.x + bb.x,
                (O[eb][r * 2 + 1] - mean) * rs * gg.y + bb.y);
        }
    }
}

// -------- K5: output projection (HMMA) + bias + residual + final LN*mask ----
__global__ void __launch_bounds__(256, 1) outproj_h_k(
    const float* __restrict__ out_b, const float* __restrict__ x,
    const float* __restrict__ mask,
    const float* __restrict__ go, const float* __restrict__ bo,
    float* __restrict__ out)
{
    extern __shared__ char smem[];
    const int m0 = blockIdx.x * 128;
    const int tid = threadIdx.x, lane = tid & 31, warp = tid >> 5;
    const int wm = warp & 3, wn = warp >> 2;
    const __half* A = g_yh + (size_t)m0 * (H_ * E_);
    float acc[2][16][4];
    hgemm_main(A, H_ * E_, g_w1h, 16, smem, acc);

    __syncthreads();
    float* red = (float*)smem;

    #pragma unroll
    for (int mi = 0; mi < 2; mi++){
        int rl0 = wm * 32 + mi * 16 + (lane >> 2), rl1 = rl0 + 8;
        int r0 = m0 + rl0, r1 = m0 + rl1;
        float s0 = 0.f, q0 = 0.f, s1 = 0.f, q1 = 0.f;
        #pragma unroll
        for (int nb = 0; nb < 8; nb++)
            #pragma unroll
            for (int t2 = 0; t2 < 2; t2++){
                int col = wn * 128 + nb * 16 + t2 * 8 + (lane & 3) * 2;
                float* a = acc[mi][nb * 2 + t2];
                float b0 = out_b[col], b1 = out_b[col + 1];
                float2 x0 = *(const float2*)&x[(size_t)r0 * D_ + col];
                float2 x1 = *(const float2*)&x[(size_t)r1 * D_ + col];
                a[0] += b0 + x0.x; a[1] += b1 + x0.y;
                a[2] += b0 + x1.x; a[3] += b1 + x1.y;
                s0 += a[0] + a[1]; q0 += a[0]*a[0] + a[1]*a[1];
                s1 += a[2] + a[3]; q1 += a[2]*a[2] + a[3]*a[3];
            }
        #pragma unroll
        for (int o = 1; o <= 2; o <<= 1) {
            s0 += __shfl_xor_sync(0xffffffffu, s0, o);
            q0 += __shfl_xor_sync(0xffffffffu, q0, o);
            s1 += __shfl_xor_sync(0xffffffffu, s1, o);
            q1 += __shfl_xor_sync(0xffffffffu, q1, o);
        }
        if ((lane & 3) == 0) {
            red[rl0 * 2 + wn] = s0;  red[256 + rl0 * 2 + wn] = q0;
            red[rl1 * 2 + wn] = s1;  red[256 + rl1 * 2 + wn] = q1;
        }
    }
    __syncthreads();

    #pragma unroll
    for (int mi = 0; mi < 2; mi++){
        int rl0 = wm * 32 + mi * 16 + (lane >> 2), rl1 = rl0 + 8;
        int r0 = m0 + rl0, r1 = m0 + rl1;
        float sA = red[rl0 * 2] + red[rl0 * 2 + 1];
        float qA = red[256 + rl0 * 2] + red[256 + rl0 * 2 + 1];
        float sB = red[rl1 * 2] + red[rl1 * 2 + 1];
        float qB = red[256 + rl1 * 2] + red[256 + rl1 * 2 + 1];
        float mean0 = sA * (1.f/256.f), var0 = qA * (1.f/256.f) - mean0 * mean0;
        float mean1 = sB * (1.f/256.f), var1 = qB * (1.f/256.f) - mean1 * mean1;
        float rs0 = rsqrtf(var0 + EPS_), rs1 = rsqrtf(var1 + EPS_);
        float mv0 = (mask[r0] == PADV) ? 0.f : 1.f;
        float mv1 = (mask[r1] == PADV) ? 0.f : 1.f;
        #pragma unroll
        for (int nb = 0; nb < 8; nb++)
            #pragma unroll
            for (int t2 = 0; t2 < 2; t2++){
                int col = wn * 128 + nb * 16 + t2 * 8 + (lane & 3) * 2;
                const float* a = acc[mi][nb * 2 + t2];
                float2 gg = *(const float2*)&go[col];
                float2 bb = *(const float2*)&bo[col];
                *(float2*)&out[(size_t)r0 * E_ + col] =
                    make_float2(((a[0]-mean0)*rs0*gg.x+bb.x)*mv0, ((a[1]-mean0)*rs0*gg.y+bb.y)*mv0);
                *(float2*)&out[(size_t)r1 * E_ + col] =
                    make_float2(((a[2]-mean1)*rs1*gg.x+bb.x)*mv1, ((a[3]-mean1)*rs1*gg.y+bb.y)*mv1);
            }
    }
}

// ---------------- launch ------------------------------------------------------
extern "C" void kernel_launch(void* const* d_in, const int* in_sizes, int n_in,
                              void* d_out, int out_size)
{
    (void)in_sizes; (void)n_in; (void)out_size;
    const float* x     = (const float*)d_in[0];
    const float* mask  = (const float*)d_in[1];
    const float* Wq    = (const float*)d_in[2];
    const float* Wk    = (const float*)d_in[3];
    const float* Wv    = (const float*)d_in[4];
    const float* Wg    = (const float*)d_in[5];
    const float* out_w = (const float*)d_in[6];
    const float* out_b = (const float*)d_in[7];
    const float* g_in  = (const float*)d_in[8];
    const float* b_in  = (const float*)d_in[9];
    const float* g_res = (const float*)d_in[10];
    const float* b_res = (const float*)d_in[11];
    const float* g_out = (const float*)d_in[12];
    const float* b_out = (const float*)d_in[13];
    float* out = (float*)d_out;

    cudaFuncSetAttribute(attn_mma_k,  cudaFuncAttributeMaxDynamicSharedMemorySize, AT_SMEM);
    cudaFuncSetAttribute(qkvg_h_k,    cudaFuncAttributeMaxDynamicSharedMemorySize, HG_SMEM);
    cudaFuncSetAttribute(outproj_h_k, cudaFuncAttributeMaxDynamicSharedMemorySize, HG_SMEM);

    prep_k<<<M_ / 8 + 5 * 256, 256>>>(x, g_in, b_in, Wq, Wk, Wv, Wg, out_w);

    dim3 g2(M_ / 128, HB_);                    // (64, 16)
    qkvg_h_k<<<g2, 256, HG_SMEM>>>();

    dim3 g3(N_ / 128, HB_);                    // (16, 16)
    attn_mma_k<<<g3, 256, AT_SMEM>>>(mask, x, g_res, b_res);

    outproj_h_k<<<M_ / 128, 256, HG_SMEM>>>(out_b, x, mask, g_out, b_out, out);
}

// round 12
// speedup vs baseline: 1.1320x; 1.1320x over previous
#include <cuda_runtime.h>
#include <cuda_fp16.h>
#include <math.h>
#include <stdint.h>

#define B_  4
#define N_  2048
#define D_  256
#define H_  4
#define E_  256
#define M_  (B_*N_)          // 8192 rows
#define HB_ (H_*B_)          // 16
#define PADV (-2.0f)
#define EPS_ 1e-6f
#define CL2E 0.09016844f     // (1/sqrt(256)) * log2(e)  — folded into Q

// ---------------- scratch (device globals; no runtime alloc) ----------------
__device__ __half g_xnh[(size_t)M_*D_];          // LN(x) fp16
__device__ __half g_qh [(size_t)HB_*N_*E_];      // Q*CL2E fp16 [h][m][e]
__device__ __half g_kh [(size_t)HB_*N_*E_];      // K fp16 [h][m][e]
__device__ __half g_vt [(size_t)HB_*E_*N_];      // V^T fp16 [h][b][e][n]
__device__ __half g_gth[(size_t)HB_*N_*E_];      // gate pre-activation fp16
__device__ __half g_oh [(size_t)HB_*N_*E_];      // attention output fp16
__device__ __half g_yh [(size_t)M_*H_*E_];       // concat fp16 [m][h*E+e]
__device__ __half g_wh [(size_t)4*H_*D_*E_];     // qkvg weights fp16 [t][h][d][e]
__device__ __half g_w1h[(size_t)H_*E_*E_];       // out_w fp16, rows permuted to [h*E+e]

// =================== PTX helpers (compute_103-safe) ===================
__device__ __forceinline__ uint32_t s2u(const void* p){
    uint32_t a;
    asm("{ .reg .u64 t; cvta.to.shared.u64 t, %1; cvt.u32.u64 %0, t; }" : "=r"(a) : "l"(p));
    return a;
}
__device__ __forceinline__ void cp16(uint32_t s, const void* g){
    asm volatile("cp.async.cg.shared.global [%0], [%1], 16;" :: "r"(s), "l"(g));
}
__device__ __forceinline__ void cp_commit(){ asm volatile("cp.async.commit_group;" ::: "memory"); }
template<int NN> __device__ __forceinline__ void cp_wait(){
    asm volatile("cp.async.wait_group %0;" :: "n"(NN) : "memory");
}
__device__ __forceinline__ void ldsm_x4(uint32_t& r0, uint32_t& r1, uint32_t& r2, uint32_t& r3, uint32_t addr){
    asm volatile("ldmatrix.sync.aligned.m8n8.x4.shared.b16 {%0,%1,%2,%3}, [%4];"
        : "=r"(r0), "=r"(r1), "=r"(r2), "=r"(r3) : "r"(addr));
}
__device__ __forceinline__ void ldsm_x2(uint32_t& r0, uint32_t& r1, uint32_t addr){
    asm volatile("ldmatrix.sync.aligned.m8n8.x2.shared.b16 {%0,%1}, [%2];"
        : "=r"(r0), "=r"(r1) : "r"(addr));
}
__device__ __forceinline__ void ldsm_x4t(uint32_t& r0, uint32_t& r1, uint32_t& r2, uint32_t& r3, uint32_t addr){
    asm volatile("ldmatrix.sync.aligned.m8n8.x4.trans.shared.b16 {%0,%1,%2,%3}, [%4];"
        : "=r"(r0), "=r"(r1), "=r"(r2), "=r"(r3) : "r"(addr));
}
__device__ __forceinline__ void mma16816(float c[4], uint32_t a0, uint32_t a1, uint32_t a2, uint32_t a3,
                                         uint32_t b0, uint32_t b1){
    asm volatile("mma.sync.aligned.m16n8k16.row.col.f32.f16.f16.f32 "
        "{%0,%1,%2,%3}, {%4,%5,%6,%7}, {%8,%9}, {%0,%1,%2,%3};"
        : "+f"(c[0]), "+f"(c[1]), "+f"(c[2]), "+f"(c[3])
        : "r"(a0), "r"(a1), "r"(a2), "r"(a3), "r"(b0), "r"(b1));
}
// fp16-accumulator MMA (2x rate)
__device__ __forceinline__ void mma16816h(uint32_t c[2], uint32_t a0, uint32_t a1, uint32_t a2, uint32_t a3,
                                          uint32_t b0, uint32_t b1){
    asm volatile("mma.sync.aligned.m16n8k16.row.col.f16.f16.f16.f16 "
        "{%0,%1}, {%2,%3,%4,%5}, {%6,%7}, {%0,%1};"
        : "+r"(c[0]), "+r"(c[1])
        : "r"(a0), "r"(a1), "r"(a2), "r"(a3), "r"(b0), "r"(b1));
}
__device__ __forceinline__ uint32_t pack2(float hi, float lo){
    uint32_t d; asm("cvt.rn.f16x2.f32 %0, %1, %2;" : "=r"(d) : "f"(hi), "f"(lo)); return d;
}
__device__ __forceinline__ uint32_t ex2h2(uint32_t a){
    uint32_t d; asm("ex2.approx.f16x2 %0, %1;" : "=r"(d) : "r"(a)); return d;
}
__device__ __forceinline__ uint32_t mulh2(uint32_t a, uint32_t b){
    uint32_t d; asm("mul.f16x2 %0, %1, %2;" : "=r"(d) : "r"(a), "r"(b)); return d;
}

// ---------------- warp row-reduction helper ----------------------------------
__device__ __forceinline__ void warp_meanvar(float s, float s2, float& mean, float& var){
    #pragma unroll
    for (int o = 16; o; o >>= 1) {
        s  += __shfl_xor_sync(0xffffffffu, s,  o);
        s2 += __shfl_xor_sync(0xffffffffu, s2, o);
    }
    mean = s * (1.0f / 256.0f);
    var  = s2 * (1.0f / 256.0f) - mean * mean;
}

// ---------------- K1: fused input LN (warp/row) + weight fp16 conversion -----
__global__ void __launch_bounds__(256) prep_k(const float* __restrict__ x,
                        const float* __restrict__ g, const float* __restrict__ b,
                        const float* __restrict__ Wq, const float* __restrict__ Wk,
                        const float* __restrict__ Wv, const float* __restrict__ Wg,
                        const float* __restrict__ ow) {
    if (blockIdx.x < M_ / 8) {
        int row = blockIdx.x * 8 + (threadIdx.x >> 5);
        int lane = threadIdx.x & 31;
        const float4* xr = (const float4*)(x + (size_t)row * D_) + lane * 2;
        float4 v0 = xr[0], v1 = xr[1];
        float s  = v0.x + v0.y + v0.z + v0.w + v1.x + v1.y + v1.z + v1.w;
        float s2 = v0.x*v0.x + v0.y*v0.y + v0.z*v0.z + v0.w*v0.w
                 + v1.x*v1.x + v1.y*v1.y + v1.z*v1.z + v1.w*v1.w;
        float mean, var; warp_meanvar(s, s2, mean, var);
        float rs = rsqrtf(var + EPS_);
        float4 g0 = ((const float4*)g)[lane*2], g1 = ((const float4*)g)[lane*2+1];
        float4 b0 = ((const float4*)b)[lane*2], b1 = ((const float4*)b)[lane*2+1];
        uint32_t o[4];
        o[0] = pack2((v0.y-mean)*rs*g0.y+b0.y, (v0.x-mean)*rs*g0.x+b0.x);
        o[1] = pack2((v0.w-mean)*rs*g0.w+b0.w, (v0.z-mean)*rs*g0.z+b0.z);
        o[2] = pack2((v1.y-mean)*rs*g1.y+b1.y, (v1.x-mean)*rs*g1.x+b1.x);
        o[3] = pack2((v1.w-mean)*rs*g1.w+b1.w, (v1.z-mean)*rs*g1.z+b1.z);
        *(uint4*)(g_xnh + (size_t)row * D_ + lane * 8) = *(uint4*)o;
    } else {
        int wb = blockIdx.x - M_ / 8;
        int t = wb >> 8;
        const float* src = (t == 0) ? Wq : (t == 1) ? Wk : (t == 2) ? Wv : (t == 3) ? Wg : ow;
        int idx = ((wb & 255) * 256 + threadIdx.x) * 4;
        float4 v = *(const float4*)(src + idx);
        __half2 h0 = __floats2half2_rn(v.x, v.y), h1 = __floats2half2_rn(v.z, v.w);
        if (t < 4) {
            __half2* d2 = (__half2*)(g_wh + (size_t)t * (H_ * D_ * E_) + idx);
            d2[0] = h0; d2[1] = h1;
        } else {
            int rr = idx >> 8, col = idx & 255;       // src row = e*H + h
            int e = rr >> 2, h = rr & 3;
            __half2* d2 = (__half2*)(g_w1h + (size_t)(h * E_ + e) * E_ + col);
            d2[0] = h0; d2[1] = h1;
        }
    }
}

// =================== HMMA GEMM mainloop: 128 x 256 tile, m32n128/warp ========
#define HG_LDA 72
#define HG_LDB 264
#define HG_BS_OFF 36864
#define HG_SMEM 104448
#define VT_LDT 136

__device__ __forceinline__ void hg_load(const __half* A, int ldA, const __half* Bg,
                                        uint32_t sA, uint32_t sB, int c, int buf, int tid){
    #pragma unroll
    for (int it = 0; it < 4; it++){
        int idx = tid + it * 256;
        int row = idx >> 3, cg = idx & 7;
        cp16(sA + (uint32_t)(buf * 128 * HG_LDA + row * HG_LDA + cg * 8) * 2,
             A + (size_t)row * ldA + c * 64 + cg * 8);
    }
    #pragma unroll
    for (int it = 0; it < 8; it++){
        int idx = tid + it * 256;
        int row = idx >> 5, cg = idx & 31;
        cp16(sB + (uint32_t)(buf * 64 * HG_LDB + row * HG_LDB + cg * 8) * 2,
             Bg + (size_t)(c * 64 + row) * 256 + cg * 8);
    }
    cp_commit();
}

__device__ __forceinline__ void hgemm_main(const __half* A, int ldA, const __half* Bg,
                                           int NC, char* smem, float acc[2][16][4]){
    const int tid = threadIdx.x, lane = tid & 31, warp = tid >> 5;
    const int wm = warp & 3, wn = warp >> 2;
    const uint32_t sA = s2u(smem), sB = s2u(smem + HG_BS_OFF);
    #pragma unroll
    for (int mi = 0; mi < 2; mi++)
        #pragma unroll
        for (int i = 0; i < 16; i++)
            #pragma unroll
            for (int j = 0; j < 4; j++) acc[mi][i][j] = 0.f;

    hg_load(A, ldA, Bg, sA, sB, 0, 0, tid);
    hg_load(A, ldA, Bg, sA, sB, 1, 1, tid);

    const int grp = lane >> 3, r8 = lane & 7;
    uint32_t aoff[2];
    #pragma unroll
    for (int mi = 0; mi < 2; mi++)
        aoff[mi] = (uint32_t)((wm * 32 + mi * 16 + (lane & 15)) * HG_LDA + (lane >> 4) * 8) * 2;
    const uint32_t boff = (uint32_t)(((grp & 1) * 8 + r8) * HG_LDB + wn * 128 + ((grp & 2) ? 8 : 0)) * 2;

    for (int c = 0; c < NC; c++){
        if (c + 1 < NC) cp_wait<1>(); else cp_wait<0>();
        __syncthreads();
        const uint32_t sa = sA + (uint32_t)((c & 1) * 128 * HG_LDA * 2);
        const uint32_t sb = sB + (uint32_t)((c & 1) * 64 * HG_LDB * 2) + boff;
        #pragma unroll
        for (int ks = 0; ks < 4; ks++){
            uint32_t a[2][4];
            #pragma unroll
            for (int mi = 0; mi < 2; mi++)
                ldsm_x4(a[mi][0], a[mi][1], a[mi][2], a[mi][3], sa + aoff[mi] + (uint32_t)(ks * 32));
            #pragma unroll
            for (int nb = 0; nb < 8; nb++){
                uint32_t b0, b1, b2, b3;
                ldsm_x4t(b0, b1, b2, b3, sb + (uint32_t)(ks * 16 * HG_LDB + nb * 16) * 2);
                #pragma unroll
                for (int mi = 0; mi < 2; mi++){
                    mma16816(acc[mi][2 * nb],     a[mi][0], a[mi][1], a[mi][2], a[mi][3], b0, b1);
                    mma16816(acc[mi][2 * nb + 1], a[mi][0], a[mi][1], a[mi][2], a[mi][3], b2, b3);
                }
            }
        }
        __syncthreads();
        if (c + 2 < NC) hg_load(A, ldA, Bg, sA, sB, c + 2, c & 1, tid);
    }
}

// ---------------- K2: Q/K/V/gate projections (HMMA) --------------------------
__global__ void __launch_bounds__(256, 1) qkvg_h_k()
{
    extern __shared__ char smem[];
    const int z = blockIdx.y, h = z >> 2, t = z & 3;
    const int m0 = blockIdx.x * 128;
    const int tid = threadIdx.x, lane = tid & 31, warp = tid >> 5;
    const int wm = warp & 3, wn = warp >> 2;
    const __half* A = g_xnh + (size_t)m0 * D_;
    const __half* W = g_wh + ((size_t)t * H_ + h) * D_ * E_;
    float acc[2][16][4];
    hgemm_main(A, D_, W, 4, smem, acc);

    if (t != 2) {
        __half* C = (t == 0 ? g_qh : t == 1 ? g_kh : g_gth) + (size_t)h * M_ * E_;
        const float sc = (t == 0) ? CL2E : 1.0f;
        #pragma unroll
        for (int mi = 0; mi < 2; mi++){
            int r0 = m0 + wm * 32 + mi * 16 + (lane >> 2), r1 = r0 + 8;
            #pragma unroll
            for (int nb = 0; nb < 8; nb++)
                #pragma unroll
                for (int t2 = 0; t2 < 2; t2++){
                    int col = wn * 128 + nb * 16 + t2 * 8 + (lane & 3) * 2;
                    const float* a = acc[mi][nb * 2 + t2];
                    *(__half2*)&C[(size_t)r0 * E_ + col] = __floats2half2_rn(a[0] * sc, a[1] * sc);
                    *(__half2*)&C[(size_t)r1 * E_ + col] = __floats2half2_rn(a[2] * sc, a[3] * sc);
                }
        }
    } else {
        __half* st = (__half*)smem;
        __syncthreads();
        #pragma unroll
        for (int mi = 0; mi < 2; mi++){
            int r0 = wm * 32 + mi * 16 + (lane >> 2), r1 = r0 + 8;
            #pragma unroll
            for (int nb = 0; nb < 8; nb++)
                #pragma unroll
                for (int t2 = 0; t2 < 2; t2++){
                    int col = wn * 128 + nb * 16 + t2 * 8 + (lane & 3) * 2;
                    const float* a = acc[mi][nb * 2 + t2];
                    st[(col    ) * VT_LDT + r0] = __float2half_rn(a[0]);
                    st[(col + 1) * VT_LDT + r0] = __float2half_rn(a[1]);
                    st[(col    ) * VT_LDT + r1] = __float2half_rn(a[2]);
                    st[(col + 1) * VT_LDT + r1] = __float2half_rn(a[3]);
                }
        }
        __syncthreads();
        const int bidx = m0 >> 11, n0 = m0 & (N_ - 1);
        __half* dst = g_vt + (size_t)(h * B_ + bidx) * E_ * N_;
        #pragma unroll
        for (int i = 0; i < 16; i++){
            int chunk = tid + i * 256;
            int e = chunk >> 4, off = (chunk & 15) * 8;
            *(uint4*)&dst[(size_t)e * N_ + n0 + off] = *(uint4*)&st[e * VT_LDT + off];
        }
    }
}

// =================== K3: HMMA flash attention (S/PV pipelined, fp16 S) =======
#define LDK 264
#define LDV 72
#define AT_Q   0
#define AT_K   (128 * LDK)                 // 2 bufs of 64*LDK
#define AT_V   (AT_K + 2 * 64 * LDK)       // 2 bufs of 256*LDV
#define AT_ONE (AT_V + 2 * 256 * LDV)      // 8*LDV (row0=ones)
#define AT_KM  (AT_ONE + 8 * LDV)          // 2048 halves (1024 u32) full key mask
#define AT_H   (AT_KM + 2048)
#define AT_SMEM (AT_H * 2)                 // 214144 bytes

__device__ __forceinline__ void expconv_h(const uint32_t S[8][2], uint32_t pa[4][4],
                                          const uint32_t* kmbase, int lane){
    #pragma unroll
    for (int nb = 0; nb < 8; nb++) {
        uint32_t km = kmbase[nb * 4 + (lane & 3)];
        pa[nb >> 1][(nb & 1) * 2]     = mulh2(ex2h2(S[nb][0]), km);
        pa[nb >> 1][(nb & 1) * 2 + 1] = mulh2(ex2h2(S[nb][1]), km);
    }
}

__global__ void __launch_bounds__(256, 1) attn_mma_k(const float* __restrict__ mask)
{
    extern __shared__ __half sm[];
    const int tid = threadIdx.x, lane = tid & 31, warp = tid >> 5;
    const int qt = blockIdx.x, hb = blockIdx.y, bidx = hb & (B_ - 1);
    const int qbase = qt * 128;
    const __half* Qg = g_qh + (size_t)hb * N_ * E_ + (size_t)qbase * E_;
    const __half* Kg = g_kh + (size_t)hb * N_ * E_;
    const __half* Vt = g_vt + (size_t)hb * E_ * N_;
    __half* Og = g_oh + (size_t)hb * N_ * E_;
    const float* mrow = mask + (size_t)bidx * N_;

    const uint32_t sQ = s2u(sm + AT_Q);
    const uint32_t sK = s2u(sm + AT_K);
    const uint32_t sV = s2u(sm + AT_V);
    const uint32_t sONE = s2u(sm + AT_ONE);
    uint32_t* kmarr = (uint32_t*)(sm + AT_KM);

    if (tid < 288) ((uint32_t*)(sm + AT_ONE))[tid] = (tid < 36) ? 0x3C003C00u : 0u;
    #pragma unroll
    for (int j = 0; j < 4; j++) {
        float a = mrow[tid * 8 + 2 * j], b = mrow[tid * 8 + 2 * j + 1];
        __half2 km = __floats2half2_rn((a == PADV) ? 0.f : 1.f, (b == PADV) ? 0.f : 1.f);
        kmarr[tid * 4 + j] = *(uint32_t*)&km;
    }

    #pragma unroll
    for (int it = 0; it < 16; it++) {
        int idx = tid + it * 256;
        int row = idx >> 5, c = idx & 31;
        cp16(sQ + (uint32_t)(row * LDK + c * 8) * 2, Qg + (size_t)row * E_ + c * 8);
    }
    cp_commit();
    #pragma unroll
    for (int buf = 0; buf < 2; buf++) {
        #pragma unroll
        for (int it = 0; it < 8; it++) {
            int idx = tid + it * 256;
            int row = idx >> 5, c = idx & 31;
            cp16(sK + (uint32_t)(buf * 64 * LDK + row * LDK + c * 8) * 2,
                 Kg + (size_t)(buf * 64 + row) * E_ + c * 8);
        }
        cp_commit();
        #pragma unroll
        for (int it = 0; it < 8; it++) {
            int idx = tid + it * 256;
            int e = idx >> 3, c = idx & 7;
            cp16(sV + (uint32_t)(buf * 256 * LDV + e * LDV + c * 8) * 2,
                 Vt + (size_t)e * N_ + buf * 64 + c * 8);
        }
        cp_commit();
    }

    const int grp = lane >> 3, r8 = lane & 7;
    const int moff = (grp & 2) ? 8 : 0;
    const int koff = (grp & 1) ? 8 : 0;
    const uint32_t qaddr0 = sQ + (uint32_t)((warp * 16 + (lane & 15)) * LDK + (lane >> 4) * 8) * 2;
    const uint32_t kaddr0 = sK + (uint32_t)((moff + r8) * LDK + koff) * 2;
    const uint32_t vaddr0 = sV + (uint32_t)((moff + r8) * LDV + koff) * 2;
    const uint32_t exaddr = sONE + (uint32_t)((lane & 7) * LDV + ((lane >> 3) & 1) * 8) * 2;

    float O[32][4];
    #pragma unroll
    for (int i = 0; i < 32; i++)
        #pragma unroll
        for (int j = 0; j < 4; j++) O[i][j] = 0.f;
    float Oex[4] = {0.f, 0.f, 0.f, 0.f};
    uint32_t pa[4][4];

    cp_wait<3>();
    __syncthreads();
    {
        uint32_t S[8][2];
        #pragma unroll
        for (int i = 0; i < 8; i++) { S[i][0] = 0u; S[i][1] = 0u; }
        #pragma unroll
        for (int ks = 0; ks < 16; ks++) {
            uint32_t q0, q1, q2, q3;
            ldsm_x4(q0, q1, q2, q3, qaddr0 + (uint32_t)(ks * 32));
            #pragma unroll
            for (int nbp = 0; nbp < 4; nbp++) {
                uint32_t b0, b1, b2, b3;
                ldsm_x4(b0, b1, b2, b3, kaddr0 + (uint32_t)(nbp * 16 * LDK * 2 + ks * 32));
                mma16816h(S[2 * nbp],     q0, q1, q2, q3, b0, b1);
                mma16816h(S[2 * nbp + 1], q0, q1, q2, q3, b2, b3);
            }
        }
        expconv_h(S, pa, kmarr, lane);
    }

    for (int kc = 0; kc < 32; kc++) {
        if (kc == 31) cp_wait<0>(); else cp_wait<1>();
        __syncthreads();

        if (kc + 2 < 32) {
            const int nb2 = kc * 64 + 128;
            #pragma unroll
            for (int it = 0; it < 8; it++) {
                int idx = tid + it * 256;
                int row = idx >> 5, c = idx & 31;
                cp16(sK + (uint32_t)((kc & 1) * 64 * LDK + row * LDK + c * 8) * 2,
                     Kg + (size_t)(nb2 + row) * E_ + c * 8);
            }
            cp_commit();
        }

        const uint32_t kbN = kaddr0 + (uint32_t)(((kc + 1) & 1) * 64 * LDK) * 2;
        const uint32_t vb  = vaddr0 + (uint32_t)((kc & 1) * 256 * LDV) * 2;

        if (kc < 31) {
            uint32_t S[8][2];
            #pragma unroll
            for (int i = 0; i < 8; i++) { S[i][0] = 0u; S[i][1] = 0u; }
            #pragma unroll
            for (int i = 0; i < 16; i++) {
                uint32_t q0, q1, q2, q3;
                ldsm_x4(q0, q1, q2, q3, qaddr0 + (uint32_t)(i * 32));
                #pragma unroll
                for (int nbp = 0; nbp < 4; nbp++) {
                    uint32_t b0, b1, b2, b3;
                    ldsm_x4(b0, b1, b2, b3, kbN + (uint32_t)(nbp * 16 * LDK * 2 + i * 32));
                    mma16816h(S[2 * nbp],     q0, q1, q2, q3, b0, b1);
                    mma16816h(S[2 * nbp + 1], q0, q1, q2, q3, b2, b3);
                }
                #pragma unroll
                for (int ks2 = 0; ks2 < 4; ks2++) {
                    uint32_t v0, v1, v2, v3;
                    ldsm_x4(v0, v1, v2, v3, vb + (uint32_t)(i * 16 * LDV * 2 + ks2 * 32));
                    mma16816(O[2 * i],     pa[ks2][0], pa[ks2][1], pa[ks2][2], pa[ks2][3], v0, v1);
                    mma16816(O[2 * i + 1], pa[ks2][0], pa[ks2][1], pa[ks2][2], pa[ks2][3], v2, v3);
                }
            }
            #pragma unroll
            for (int ks2 = 0; ks2 < 4; ks2++) {
                uint32_t e0, e1;
                ldsm_x2(e0, e1, exaddr + (uint32_t)(ks2 * 32));
                mma16816(Oex, pa[ks2][0], pa[ks2][1], pa[ks2][2], pa[ks2][3], e0, e1);
            }
            expconv_h(S, pa, kmarr + (kc + 1) * 32, lane);

            __syncthreads();
            if (kc + 2 < 32) {
                const int nb2 = kc * 64 + 128;
                #pragma unroll
                for (int it = 0; it < 8; it++) {
                    int idx = tid + it * 256;
                    int e = idx >> 3, c = idx & 7;
                    cp16(sV + (uint32_t)((kc & 1) * 256 * LDV + e * LDV + c * 8) * 2,
                         Vt + (size_t)e * N_ + nb2 + c * 8);
                }
                cp_commit();
            }
        } else {
            #pragma unroll
            for (int i = 0; i < 16; i++) {
                #pragma unroll
                for (int ks2 = 0; ks2 < 4; ks2++) {
                    uint32_t v0, v1, v2, v3;
                    ldsm_x4(v0, v1, v2, v3, vb + (uint32_t)(i * 16 * LDV * 2 + ks2 * 32));
                    mma16816(O[2 * i],     pa[ks2][0], pa[ks2][1], pa[ks2][2], pa[ks2][3], v0, v1);
                    mma16816(O[2 * i + 1], pa[ks2][0], pa[ks2][1], pa[ks2][2], pa[ks2][3], v2, v3);
                }
            }
            #pragma unroll
            for (int ks2 = 0; ks2 < 4; ks2++) {
                uint32_t e0, e1;
                ldsm_x2(e0, e1, exaddr + (uint32_t)(ks2 * 32));
                mma16816(Oex, pa[ks2][0], pa[ks2][1], pa[ks2][2], pa[ks2][3], e0, e1);
            }
        }
    }

    float l0 = __shfl_sync(0xffffffffu, Oex[0], lane & ~3);
    float l1 = __shfl_sync(0xffffffffu, Oex[2], lane & ~3);
    const int r0 = qbase + warp * 16 + (lane >> 2);
    const int r1 = r0 + 8;
    float inv0 = ((mrow[r0] == PADV) ? 0.f : 1.f) / fmaxf(l0, 1e-30f);
    float inv1 = ((mrow[r1] == PADV) ? 0.f : 1.f) / fmaxf(l1, 1e-30f);
    #pragma unroll
    for (int eb = 0; eb < 32; eb++) {
        int col = eb * 8 + (lane & 3) * 2;
        *(__half2*)&Og[(size_t)r0 * E_ + col] = __floats2half2_rn(O[eb][0] * inv0, O[eb][1] * inv0);
        *(__half2*)&Og[(size_t)r1 * E_ + col] = __floats2half2_rn(O[eb][2] * inv1, O[eb][3] * inv1);
    }
}

// ---------------- K4: gate + residual + per-head LN + concat (warp/row) -----
__global__ void __launch_bounds__(256) epi_k(const float* __restrict__ x,
                      const float* __restrict__ gr, const float* __restrict__ br)
{
    int row = blockIdx.x * 8 + (threadIdx.x >> 5);   // row = m*4 + h
    int lane = threadIdx.x & 31;
    int m = row >> 2, h = row & 3;
    size_t off = ((size_t)h * M_ + m) * E_ + lane * 8;
    uint4 ou = *(uint4*)(g_oh + off);
    uint4 gu = *(uint4*)(g_gth + off);
    const float4* xr = (const float4*)(x + (size_t)m * D_) + lane * 2;
    float4 x0 = xr[0], x1 = xr[1];
    float xv[8] = {x0.x, x0.y, x0.z, x0.w, x1.x, x1.y, x1.z, x1.w};
    float t[8];
    const uint32_t* op = (const uint32_t*)&ou;
    const uint32_t* gp = (const uint32_t*)&gu;
    float s = 0.f, s2 = 0.f;
    #pragma unroll
    for (int j = 0; j < 4; j++) {
        float2 o2 = __half22float2(*(const __half2*)&op[j]);
        float2 g2 = __half22float2(*(const __half2*)&gp[j]);
        float sg0 = 1.f / (1.f + __expf(-g2.x));
        float sg1 = 1.f / (1.f + __expf(-g2.y));
        t[2*j]   = o2.x * sg0 + xv[2*j];
        t[2*j+1] = o2.y * sg1 + xv[2*j+1];
        s += t[2*j] + t[2*j+1];
        s2 += t[2*j]*t[2*j] + t[2*j+1]*t[2*j+1];
    }
    float mean, var; warp_meanvar(s, s2, mean, var);
    float rs = rsqrtf(var + EPS_);
    float4 gr0 = ((const float4*)gr)[lane*2], gr1 = ((const float4*)gr)[lane*2+1];
    float4 br0 = ((const float4*)br)[lane*2], br1 = ((const float4*)br)[lane*2+1];
    float grv[8] = {gr0.x, gr0.y, gr0.z, gr0.w, gr1.x, gr1.y, gr1.z, gr1.w};
    float brv[8] = {br0.x, br0.y, br0.z, br0.w, br1.x, br1.y, br1.z, br1.w};
    uint32_t outv[4];
    #pragma unroll
    for (int j = 0; j < 4; j++)
        outv[j] = pack2((t[2*j+1]-mean)*rs*grv[2*j+1]+brv[2*j+1],
                        (t[2*j]  -mean)*rs*grv[2*j]  +brv[2*j]);
    *(uint4*)(g_yh + (size_t)m * (H_ * E_) + h * E_ + lane * 8) = *(uint4*)outv;
}

// ===== K5: output projection, 64-row tiles (m32n64/warp) + final LN*mask =====
#define OP_LDA 72
#define OP_LDB 264
#define OP_BS_OFF (2 * 64 * OP_LDA * 2)    // 18432
#define OP_SMEM (OP_BS_OFF + 2 * 64 * OP_LDB * 2)  // 86016

__device__ __forceinline__ void op_load(const __half* A, const __half* Bg,
                                        uint32_t sA, uint32_t sB, int c, int buf, int tid){
    #pragma unroll
    for (int it = 0; it < 2; it++){
        int idx = tid + it * 256;
        int row = idx >> 3, cg = idx & 7;
        cp16(sA + (uint32_t)(buf * 64 * OP_LDA + row * OP_LDA + cg * 8) * 2,
             A + (size_t)row * (H_ * E_) + c * 64 + cg * 8);
    }
    #pragma unroll
    for (int it = 0; it < 8; it++){
        int idx = tid + it * 256;
        int row = idx >> 5, cg = idx & 31;
        cp16(sB + (uint32_t)(buf * 64 * OP_LDB + row * OP_LDB + cg * 8) * 2,
             Bg + (size_t)(c * 64 + row) * 256 + cg * 8);
    }
    cp_commit();
}

__global__ void __launch_bounds__(256) outproj_h_k(
    const float* __restrict__ out_b, const float* __restrict__ x,
    const float* __restrict__ mask,
    const float* __restrict__ go, const float* __restrict__ bo,
    float* __restrict__ out)
{
    extern __shared__ char smem[];
    const int m0 = blockIdx.x * 64;
    const int tid = threadIdx.x, lane = tid & 31, warp = tid >> 5;
    const int wm = warp & 1, wn = warp >> 1;      // 2 m-groups x 4 n-groups
    const __half* A = g_yh + (size_t)m0 * (H_ * E_);
    const uint32_t sA = s2u(smem), sB = s2u(smem + OP_BS_OFF);

    float acc[2][8][4];
    #pragma unroll
    for (int mi = 0; mi < 2; mi++)
        #pragma unroll
        for (int i = 0; i < 8; i++)
            #pragma unroll
            for (int j = 0; j < 4; j++) acc[mi][i][j] = 0.f;

    op_load(A, g_w1h, sA, sB, 0, 0, tid);
    op_load(A, g_w1h, sA, sB, 1, 1, tid);

    const int grp = lane >> 3, r8 = lane & 7;
    uint32_t aoff[2];
    #pragma unroll
    for (int mi = 0; mi < 2; mi++)
        aoff[mi] = (uint32_t)((wm * 32 + mi * 16 + (lane & 15)) * OP_LDA + (lane >> 4) * 8) * 2;
    const uint32_t boff = (uint32_t)(((grp & 1) * 8 + r8) * OP_LDB + wn * 64 + ((grp & 2) ? 8 : 0)) * 2;

    for (int c = 0; c < 16; c++){
        if (c + 1 < 16) cp_wait<1>(); else cp_wait<0>();
        __syncthreads();
        const uint32_t sa = sA + (uint32_t)((c & 1) * 64 * OP_LDA * 2);
        const uint32_t sb = sB + (uint32_t)((c & 1) * 64 * OP_LDB * 2) + boff;
        #pragma unroll
        for (int ks = 0; ks < 4; ks++){
            uint32_t a[2][4];
            #pragma unroll
            for (int mi = 0; mi < 2; mi++)
                ldsm_x4(a[mi][0], a[mi][1], a[mi][2], a[mi][3], sa + aoff[mi] + (uint32_t)(ks * 32));
            #pragma unroll
            for (int nb = 0; nb < 4; nb++){
                uint32_t b0, b1, b2, b3;
                ldsm_x4t(b0, b1, b2, b3, sb + (uint32_t)(ks * 16 * OP_LDB + nb * 16) * 2);
                #pragma unroll
                for (int mi = 0; mi < 2; mi++){
                    mma16816(acc[mi][2 * nb],     a[mi][0], a[mi][1], a[mi][2], a[mi][3], b0, b1);
                    mma16816(acc[mi][2 * nb + 1], a[mi][0], a[mi][1], a[mi][2], a[mi][3], b2, b3);
                }
            }
        }
        __syncthreads();
        if (c + 2 < 16) op_load(A, g_w1h, sA, sB, c + 2, c & 1, tid);
    }

    __syncthreads();
    float* red = (float*)smem;             // red[0..255]: s[row][wn]; red[256..511]: s2

    #pragma unroll
    for (int mi = 0; mi < 2; mi++){
        int rl0 = wm * 32 + mi * 16 + (lane >> 2), rl1 = rl0 + 8;
        int r0 = m0 + rl0, r1 = m0 + rl1;
        float s0 = 0.f, q0 = 0.f, s1 = 0.f, q1 = 0.f;
        #pragma unroll
        for (int nb = 0; nb < 4; nb++)
            #pragma unroll
            for (int t2 = 0; t2 < 2; t2++){
                int col = wn * 64 + nb * 16 + t2 * 8 + (lane & 3) * 2;
                float* a = acc[mi][nb * 2 + t2];
                float b0 = out_b[col], b1 = out_b[col + 1];
                float2 x0 = *(const float2*)&x[(size_t)r0 * D_ + col];
                float2 x1 = *(const float2*)&x[(size_t)r1 * D_ + col];
                a[0] += b0 + x0.x; a[1] += b1 + x0.y;
                a[2] += b0 + x1.x; a[3] += b1 + x1.y;
                s0 += a[0] + a[1]; q0 += a[0]*a[0] + a[1]*a[1];
                s1 += a[2] + a[3]; q1 += a[2]*a[2] + a[3]*a[3];
            }
        #pragma unroll
        for (int o = 1; o <= 2; o <<= 1) {
            s0 += __shfl_xor_sync(0xffffffffu, s0, o);
            q0 += __shfl_xor_sync(0xffffffffu, q0, o);
            s1 += __shfl_xor_sync(0xffffffffu, s1, o);
            q1 += __shfl_xor_sync(0xffffffffu, q1, o);
        }
        if ((lane & 3) == 0) {
            red[rl0 * 4 + wn] = s0;  red[256 + rl0 * 4 + wn] = q0;
            red[rl1 * 4 + wn] = s1;  red[256 + rl1 * 4 + wn] = q1;
        }
    }
    __syncthreads();

    #pragma unroll
    for (int mi = 0; mi < 2; mi++){
        int rl0 = wm * 32 + mi * 16 + (lane >> 2), rl1 = rl0 + 8;
        int r0 = m0 + rl0, r1 = m0 + rl1;
        float sA_ = red[rl0*4] + red[rl0*4+1] + red[rl0*4+2] + red[rl0*4+3];
        float qA = red[256+rl0*4] + red[256+rl0*4+1] + red[256+rl0*4+2] + red[256+rl0*4+3];
        float sB_ = red[rl1*4] + red[rl1*4+1] + red[rl1*4+2] + red[rl1*4+3];
        float qB = red[256+rl1*4] + red[256+rl1*4+1] + red[256+rl1*4+2] + red[256+rl1*4+3];
        float mean0 = sA_ * (1.f/256.f), var0 = qA * (1.f/256.f) - mean0 * mean0;
        float mean1 = sB_ * (1.f/256.f), var1 = qB * (1.f/256.f) - mean1 * mean1;
        float rs0 = rsqrtf(var0 + EPS_), rs1 = rsqrtf(var1 + EPS_);
        float mv0 = (mask[r0] == PADV) ? 0.f : 1.f;
        float mv1 = (mask[r1] == PADV) ? 0.f : 1.f;
        #pragma unroll
        for (int nb = 0; nb < 4; nb++)
            #pragma unroll
            for (int t2 = 0; t2 < 2; t2++){
                int col = wn * 64 + nb * 16 + t2 * 8 + (lane & 3) * 2;
                const float* a = acc[mi][nb * 2 + t2];
                float2 gg = *(const float2*)&go[col];
                float2 bb = *(const float2*)&bo[col];
                *(float2*)&out[(size_t)r0 * E_ + col] =
                    make_float2(((a[0]-mean0)*rs0*gg.x+bb.x)*mv0, ((a[1]-mean0)*rs0*gg.y+bb.y)*mv0);
                *(float2*)&out[(size_t)r1 * E_ + col] =
                    make_float2(((a[2]-mean1)*rs1*gg.x+bb.x)*mv1, ((a[3]-mean1)*rs1*gg.y+bb.y)*mv1);
            }
    }
}

// ---------------- launch ------------------------------------------------------
extern "C" void kernel_launch(void* const* d_in, const int* in_sizes, int n_in,
                              void* d_out, int out_size)
{
    (void)in_sizes; (void)n_in; (void)out_size;
    const float* x     = (const float*)d_in[0];
    const float* mask  = (const float*)d_in[1];
    const float* Wq    = (const float*)d_in[2];
    const float* Wk    = (const float*)d_in[3];
    const float* Wv    = (const float*)d_in[4];
    const float* Wg    = (const float*)d_in[5];
    const float* out_w = (const float*)d_in[6];
    const float* out_b = (const float*)d_in[7];
    const float* g_in  = (const float*)d_in[8];
    const float* b_in  = (const float*)d_in[9];
    const float* g_res = (const float*)d_in[10];
    const float* b_res = (const float*)d_in[11];
    const float* g_out = (const float*)d_in[12];
    const float* b_out = (const float*)d_in[13];
    float* out = (float*)d_out;

    cudaFuncSetAttribute(attn_mma_k,  cudaFuncAttributeMaxDynamicSharedMemorySize, AT_SMEM);
    cudaFuncSetAttribute(qkvg_h_k,    cudaFuncAttributeMaxDynamicSharedMemorySize, HG_SMEM);
    cudaFuncSetAttribute(outproj_h_k, cudaFuncAttributeMaxDynamicSharedMemorySize, OP_SMEM);

    prep_k<<<M_ / 8 + 5 * 256, 256>>>(x, g_in, b_in, Wq, Wk, Wv, Wg, out_w);

    dim3 g2(M_ / 128, HB_);                    // (64, 16)
    qkvg_h_k<<<g2, 256, HG_SMEM>>>();

    dim3 g3(N_ / 128, HB_);                    // (16, 16)
    attn_mma_k<<<g3, 256, AT_SMEM>>>(mask);

    epi_k<<<M_ * H_ / 8, 256>>>(x, g_res, b_res);

    outproj_h_k<<<M_ / 64, 256, OP_SMEM>>>(out_b, x, mask, g_out, b_out, out);
}